// round 15
// baseline (speedup 1.0000x reference)
#include <cuda_runtime.h>
#include <cuda.h>
#include <cuda_fp16.h>
#include <math.h>

#define NPTS 100000
#define CDIM 1024
#define DDIM 256
#define THRESH 8.0f

// Scratch (no allocations allowed)
__device__ __align__(16) float g_Phi[CDIM * DDIM];
__device__ __align__(16) __half g_PhiH[CDIM * DDIM];
__device__ __align__(16) float g_p2part[8 * CDIM];   // [nblk][c] partial p2
__device__ int g_cnt;
__device__ int g_list[NPTS];
__device__ unsigned long long g_best[NPTS];

// ---------------------------------------------------------------------------
// PTX helpers (sm_100-safe: mma.sync + TMA + mbarrier only)
// ---------------------------------------------------------------------------
static __device__ __forceinline__ unsigned smem_u32(const void* p) {
    return (unsigned)__cvta_generic_to_shared(p);
}

#define SWZ128(off) ((off) ^ (((off) >> 3) & 0x70))

#define LDSM4(r0, r1, r2, r3, addr)                                            \
    asm volatile("ldmatrix.sync.aligned.m8n8.x4.shared.b16 {%0,%1,%2,%3}, [%4];" \
                 : "=r"(r0), "=r"(r1), "=r"(r2), "=r"(r3) : "r"(addr))

#define MMA16816F16(c, a, b)                                                   \
    asm volatile("mma.sync.aligned.m16n8k16.row.col.f32.f16.f16.f32 "          \
                 "{%0,%1,%2,%3}, {%4,%5,%6,%7}, {%8,%9}, {%0,%1,%2,%3};"       \
                 : "+f"((c)[0]), "+f"((c)[1]), "+f"((c)[2]), "+f"((c)[3])      \
                 : "r"((a)[0]), "r"((a)[1]), "r"((a)[2]), "r"((a)[3]),         \
                   "r"((b)[0]), "r"((b)[1]))

#define MBARRIER_INIT(mbar, cnt) \
    asm volatile("mbarrier.init.shared.b64 [%0], %1;" \
                 :: "r"((unsigned)(mbar)), "r"((unsigned)(cnt)) : "memory")
#define MBARRIER_EXPECT_TX(mbar, b) \
    asm volatile("mbarrier.arrive.expect_tx.shared.b64 _, [%0], %1;" \
                 :: "r"((unsigned)(mbar)), "r"((unsigned)(b)) : "memory")

static __device__ __forceinline__ void mbar_wait(unsigned mbar, unsigned parity) {
    asm volatile(
        "{\n\t"
        ".reg .pred P;\n\t"
        "W_%=:\n\t"
        "mbarrier.try_wait.parity.acquire.cta.shared::cta.b64 P, [%0], %1, 0x989680;\n\t"
        "@P bra D_%=;\n\t"
        "bra W_%=;\n\t"
        "D_%=:\n\t"
        "}"
        :: "r"(mbar), "r"(parity) : "memory");
}

static __device__ __forceinline__ void tma2d(unsigned dst, const CUtensorMap* map,
                                             int x, int y, unsigned mbar) {
    asm volatile(
        "cp.async.bulk.tensor.2d.shared::cta.global.tile.mbarrier::complete_tx::bytes "
        "[%0], [%1, {%2, %3}], [%4];"
        :: "r"(dst), "l"(map), "r"(x), "r"(y), "r"(mbar) : "memory");
}

// Monotonic float <-> ordered-uint encoding (min of key = min score, then idx)
static __device__ __forceinline__ unsigned f2ord(float f) {
    unsigned u = __float_as_uint(f);
    return (u & 0x80000000u) ? ~u : (u | 0x80000000u);
}
static __device__ __forceinline__ float ord2f(unsigned o) {
    unsigned u = (o & 0x80000000u) ? (o ^ 0x80000000u) : ~o;
    return __uint_as_float(u);
}

// Deterministic 8-partial sum (fixed sequential order)
static __device__ __forceinline__ float p2sum(int c) {
    float s = g_p2part[c];
#pragma unroll
    for (int j = 1; j < 8; ++j) s += g_p2part[j * CDIM + c];
    return s;
}

// ---------------------------------------------------------------------------
// Kernel 1: Phi = parents @ epsilon. Sequential k 0..1023 per element (exact,
// matches reference ordering — DO NOT reassociate; one flip fails the test).
// Epilogue: fp32 + fp16 writes + deterministic per-block p2 partial.
// ---------------------------------------------------------------------------
__global__ __launch_bounds__(256) void phi_kernel(const float* __restrict__ A,
                                                  const float* __restrict__ B) {
    __shared__ __align__(16) float As[16][34];
    __shared__ __align__(16) float Bs[16][36];
    const int tid = threadIdx.x;
    const int tx = tid & 15, ty = tid >> 4;
    const int m0 = blockIdx.y * 32;
    const int n0 = blockIdx.x * 32;
    float acc[2][2] = {};

    for (int k0 = 0; k0 < CDIM; k0 += 16) {
        __syncthreads();
        if (tid < 128) {
            int row = tid >> 2, c4 = tid & 3;
            float4 v = *reinterpret_cast<const float4*>(&A[(m0 + row) * CDIM + k0 + c4 * 4]);
            As[c4 * 4 + 0][row] = v.x;
            As[c4 * 4 + 1][row] = v.y;
            As[c4 * 4 + 2][row] = v.z;
            As[c4 * 4 + 3][row] = v.w;
        } else {
            int t = tid - 128;
            int row = t >> 3, c8 = t & 7;
            float4 v = *reinterpret_cast<const float4*>(&B[(k0 + row) * DDIM + n0 + c8 * 4]);
            Bs[row][c8 * 4 + 0] = v.x;
            Bs[row][c8 * 4 + 1] = v.y;
            Bs[row][c8 * 4 + 2] = v.z;
            Bs[row][c8 * 4 + 3] = v.w;
        }
        __syncthreads();
#pragma unroll
        for (int k = 0; k < 16; ++k) {
            float2 a01 = *reinterpret_cast<const float2*>(&As[k][ty * 2]);
            float2 b01 = *reinterpret_cast<const float2*>(&Bs[k][tx * 2]);
            acc[0][0] = fmaf(a01.x, b01.x, acc[0][0]);
            acc[0][1] = fmaf(a01.x, b01.y, acc[0][1]);
            acc[1][0] = fmaf(a01.y, b01.x, acc[1][0]);
            acc[1][1] = fmaf(a01.y, b01.y, acc[1][1]);
        }
    }
#pragma unroll
    for (int i = 0; i < 2; ++i) {
        int row = m0 + ty * 2 + i;
        float2 v = make_float2(acc[i][0], acc[i][1]);
        *reinterpret_cast<float2*>(&g_Phi[row * DDIM + n0 + tx * 2]) = v;
        *reinterpret_cast<__half2*>(&g_PhiH[row * DDIM + n0 + tx * 2]) =
            __floats2half2_rn(acc[i][0], acc[i][1]);
        // p2 partial over this block's 32 cols: 16-lane shuffle tree (tx dim)
        float s = acc[i][0] * acc[i][0] + acc[i][1] * acc[i][1];
#pragma unroll
        for (int o = 1; o < 16; o <<= 1)
            s += __shfl_xor_sync(0xFFFFFFFFu, s, o);
        if (tx == 0)
            g_p2part[blockIdx.x * CDIM + row] = s;
    }
}

// ---------------------------------------------------------------------------
// Kernel 3: single-pass fp16 mma.sync dots + argmin; Phi via TMA (SW128),
// 3-stage ring. X stored as 4 SW128 chunks. Mainloop identical to 330us R12;
// p2 now summed from g_p2part into smem once at start.
// ---------------------------------------------------------------------------
#define X_OFF     0
#define STG_OFF   65536
#define MB_OFF    114688
#define P2_OFF    114752
#define SMEM_TOTAL (P2_OFF + 4096)

__global__ __launch_bounds__(256, 2)
void dist_kernel(const float* __restrict__ X, float* __restrict__ out,
                 const __grid_constant__ CUtensorMap tmapH) {
    extern __shared__ __align__(1024) char smem[];
    const unsigned SB = smem_u32(smem);
    const unsigned MB = SB + MB_OFF;
    float* p2s = reinterpret_cast<float*>(smem + P2_OFF);
    float* red_v = reinterpret_cast<float*>(smem + STG_OFF);
    int*   red_i = reinterpret_cast<int*>(smem + STG_OFF + 8192);
    float* red_s = reinterpret_cast<float*>(smem + STG_OFF + 16384);

    const int tid = threadIdx.x;
    const int lane = tid & 31, wid = tid >> 5;
    const int wm = wid >> 2, wn = wid & 3;
    const int mBase = wm * 64, nBase = wn * 32;
    const int rowBase = blockIdx.x * 128;

    if (tid == 0) {
        MBARRIER_INIT(MB + 0, 1);
        MBARRIER_INIT(MB + 8, 1);
        MBARRIER_INIT(MB + 16, 1);
    }

    for (int i = tid; i < 128 * 128; i += 256) {
        int r = i >> 7, kp = i & 127;
        int k = kp * 2;
        int gr = rowBase + r;
        float2 v = make_float2(0.f, 0.f);
        if (gr < NPTS)
            v = *reinterpret_cast<const float2*>(&X[(size_t)gr * DDIM + k]);
        int chunk = k >> 6, kin = k & 63;
        unsigned sw = SWZ128((unsigned)(r * 128 + kin * 2));
        *reinterpret_cast<__half2*>(smem + X_OFF + chunk * 16384 + sw) =
            __floats2half2_rn(v.x, v.y);
    }
    for (int i = tid; i < CDIM; i += 256) p2s[i] = p2sum(i);
    __syncthreads();

    if (tid == 0) {
#pragma unroll
        for (int g = 0; g < 3; ++g) {
            MBARRIER_EXPECT_TX(MB + (unsigned)g * 8, 16384);
            tma2d(SB + STG_OFF + (unsigned)g * 16384, &tmapH,
                  (g & 3) * 64, (g >> 2) * 128, MB + (unsigned)g * 8);
        }
    }

    const int arow = lane & 15;
    const int ahalf = lane >> 4;
    const int brow = (lane & 7) | ((lane >> 1) & 8);
    const int bhalf = (lane >> 3) & 1;

    int rowb[4];
#pragma unroll
    for (int mt = 0; mt < 4; ++mt)
        rowb[mt] = (mBase + mt * 16 + arow) * 128;

    float bestv[8], secondv[8];
    int   besti[8];
#pragma unroll
    for (int i = 0; i < 8; ++i) {
        bestv[i] = 3.402823466e38f; secondv[i] = 3.402823466e38f; besti[i] = 0;
    }

    float acc[4][4][4];
#pragma unroll
    for (int mt = 0; mt < 4; ++mt)
#pragma unroll
        for (int nt = 0; nt < 4; ++nt)
#pragma unroll
            for (int e = 0; e < 4; ++e) acc[mt][nt][e] = 0.f;

    for (int g = 0; g < 32; ++g) {                   // g = ct*4 + kc
        const int s = g % 3;
        const int f = g / 3;
        const int kc = g & 3;
        mbar_wait(MB + (unsigned)s * 8, (unsigned)(f & 1));
        const unsigned stH = SB + STG_OFF + (unsigned)s * 16384;
        const unsigned xCh = SB + X_OFF + (unsigned)kc * 16384;
#pragma unroll
        for (int ks = 0; ks < 4; ++ks) {
            unsigned ah[4][4];
#pragma unroll
            for (int mt = 0; mt < 4; ++mt) {
                unsigned o = SWZ128((unsigned)(rowb[mt] + ks * 32 + ahalf * 16));
                LDSM4(ah[mt][0], ah[mt][1], ah[mt][2], ah[mt][3], xCh + o);
            }
            unsigned bh[4][2];
#pragma unroll
            for (int nt2 = 0; nt2 < 2; ++nt2) {
                unsigned off = (unsigned)((nBase + nt2 * 16 + brow) * 128 +
                                          ks * 32 + bhalf * 16);
                off = SWZ128(off);
                LDSM4(bh[nt2 * 2][0], bh[nt2 * 2][1],
                      bh[nt2 * 2 + 1][0], bh[nt2 * 2 + 1][1], stH + off);
            }
#pragma unroll
            for (int mt = 0; mt < 4; ++mt)
#pragma unroll
                for (int nt = 0; nt < 4; ++nt)
                    MMA16816F16(acc[mt][nt], ah[mt], bh[nt]);
        }
        __syncthreads();
        if (tid == 0 && g + 3 < 32) {
            int g2 = g + 3;
            MBARRIER_EXPECT_TX(MB + (unsigned)s * 8, 16384);
            tma2d(SB + STG_OFF + (unsigned)s * 16384, &tmapH,
                  (g2 & 3) * 64, (g2 >> 2) * 128, MB + (unsigned)s * 8);
        }
        if (kc == 3) {
            const int colBase = (g >> 2) * 128;
#pragma unroll
            for (int nt = 0; nt < 4; ++nt) {
                int c0 = colBase + nBase + nt * 8 + (lane & 3) * 2;
                float p2a = p2s[c0];
                float p2b = p2s[c0 + 1];
#pragma unroll
                for (int mt = 0; mt < 4; ++mt) {
                    float sc[4];
                    sc[0] = fmaf(-2.f, acc[mt][nt][0], p2a);
                    sc[1] = fmaf(-2.f, acc[mt][nt][1], p2b);
                    sc[2] = fmaf(-2.f, acc[mt][nt][2], p2a);
                    sc[3] = fmaf(-2.f, acc[mt][nt][3], p2b);
#pragma unroll
                    for (int e = 0; e < 4; ++e) {
                        int slot = mt * 2 + (e >> 1);
                        int c = c0 + (e & 1);
                        if (sc[e] < bestv[slot]) {
                            secondv[slot] = bestv[slot];
                            bestv[slot] = sc[e]; besti[slot] = c;
                        } else if (sc[e] < secondv[slot]) {
                            secondv[slot] = sc[e];
                        }
                        acc[mt][nt][e] = 0.f;
                    }
                }
            }
        }
    }

    __syncthreads();
#pragma unroll
    for (int mt = 0; mt < 4; ++mt)
#pragma unroll
        for (int h = 0; h < 2; ++h) {
            int r = mBase + mt * 16 + (lane >> 2) + h * 8;
            red_v[r * 16 + wn * 4 + (lane & 3)] = bestv[mt * 2 + h];
            red_i[r * 16 + wn * 4 + (lane & 3)] = besti[mt * 2 + h];
            red_s[r * 16 + wn * 4 + (lane & 3)] = secondv[mt * 2 + h];
        }
    __syncthreads();

    if (tid < 128) {
        int gr = rowBase + tid;
        if (gr < NPTS) {
            float bv = red_v[tid * 16];
            int   bi = red_i[tid * 16];
            float sv = red_s[tid * 16];
#pragma unroll
            for (int t = 1; t < 16; ++t) {
                float v  = red_v[tid * 16 + t];
                int   ii = red_i[tid * 16 + t];
                float s2 = red_s[tid * 16 + t];
                if (v < bv || (v == bv && ii < bi)) {
                    sv = fminf(s2, bv);
                    bv = v; bi = ii;
                } else {
                    sv = fminf(sv, v);
                }
            }
            if (sv - bv < THRESH) {            // near-tie -> exact refinement
                int w = atomicAdd(&g_cnt, 1);
                g_list[w] = gr;
                g_best[w] = 0xFFFFFFFFFFFFFFFFull;
            }
            const float4* xr = reinterpret_cast<const float4*>(&X[(size_t)gr * DDIM]);
            float x2 = 0.f;
#pragma unroll 8
            for (int t = 0; t < 64; ++t) {
                float4 v = xr[t];
                x2 += v.x * v.x + v.y * v.y + v.z * v.z + v.w * v.w;
            }
            float d2 = fmaxf(x2 + bv, 0.f);
            out[gr]        = (float)bi;
            out[NPTS + gr] = sqrtf(d2);
        }
    }
}

// ---------------------------------------------------------------------------
// Kernel 4a: exact fp32 refinement, BATCHED + register-blocked, 64-cent tiles.
// Task = (32-point tile) x (64-centroid tile). Thread = 2 pts x 4 cents.
// smem: xk[256][36] f32 | phk[64][68] f32 | cand[32][16] u64 | p2t[64]
// ---------------------------------------------------------------------------
#define RS_XK    0
#define RS_PH    36864
#define RS_CAND  (RS_PH + 17408)          // 54272
#define RS_P2T   (RS_CAND + 4096)         // 58368
#define RS_SMEM  (RS_P2T + 256)           // 58624

__global__ __launch_bounds__(256) void refine_score(const float* __restrict__ X) {
    extern __shared__ __align__(16) char rsm[];
    float* xk  = reinterpret_cast<float*>(rsm + RS_XK);     // [256][36]
    float* phk = reinterpret_cast<float*>(rsm + RS_PH);     // [64][68]
    unsigned long long* cand = reinterpret_cast<unsigned long long*>(rsm + RS_CAND);
    float* p2t = reinterpret_cast<float*>(rsm + RS_P2T);    // [64]

    const int tid = threadIdx.x;
    const int pg = tid & 15;         // point group: 2 points
    const int cg = tid >> 4;         // centroid group: 4 centroids (16 groups)
    const int cnt = g_cnt;
    const int ptiles = (cnt + 31) >> 5;
    const int ntask = ptiles * 16;

    for (int task = blockIdx.x; task < ntask; task += gridDim.x) {
        const int base = (task >> 4) * 32;
        const int ctb = (task & 15) * 64;
        const int pcnt = min(32, cnt - base);
        __syncthreads();                       // protect smem reuse
        // Load 32 point rows transposed into xk[k][p]; p2 tile
        for (int i = tid; i < 32 * 64; i += 256) {
            int p = i >> 6, f4 = i & 63;
            float4 v = make_float4(0.f, 0.f, 0.f, 0.f);
            if (p < pcnt)
                v = reinterpret_cast<const float4*>(
                        &X[(size_t)g_list[base + p] * DDIM])[f4];
            xk[(f4 * 4 + 0) * 36 + p] = v.x;
            xk[(f4 * 4 + 1) * 36 + p] = v.y;
            xk[(f4 * 4 + 2) * 36 + p] = v.z;
            xk[(f4 * 4 + 3) * 36 + p] = v.w;
        }
        if (tid < 64) p2t[tid] = p2sum(ctb + tid);

        float dots[2][4];
#pragma unroll
        for (int i = 0; i < 2; ++i)
#pragma unroll
            for (int j = 0; j < 4; ++j) dots[i][j] = 0.f;

        for (int ch = 0; ch < 4; ++ch) {       // k chunks of 64
            __syncthreads();
            for (int i = tid; i < 64 * 16; i += 256) {
                int c = i >> 4, f4 = i & 15;
                float4 v = reinterpret_cast<const float4*>(
                    &g_Phi[(size_t)(ctb + c) * DDIM + ch * 64])[f4];
                phk[(f4 * 4 + 0) * 68 + c] = v.x;
                phk[(f4 * 4 + 1) * 68 + c] = v.y;
                phk[(f4 * 4 + 2) * 68 + c] = v.z;
                phk[(f4 * 4 + 3) * 68 + c] = v.w;
            }
            __syncthreads();
#pragma unroll 8
            for (int kk = 0; kk < 64; ++kk) {
                float2 xv = *reinterpret_cast<const float2*>(
                    &xk[(ch * 64 + kk) * 36 + pg * 2]);
                float4 pv = *reinterpret_cast<const float4*>(
                    &phk[kk * 68 + cg * 4]);
                float xa[2] = {xv.x, xv.y};
                float pa[4] = {pv.x, pv.y, pv.z, pv.w};
#pragma unroll
                for (int i = 0; i < 2; ++i)
#pragma unroll
                    for (int j = 0; j < 4; ++j)
                        dots[i][j] = fmaf(xa[i], pa[j], dots[i][j]);
            }
        }
        // Per-thread argmin over its 4 centroids per point (c ascending)
#pragma unroll
        for (int i = 0; i < 2; ++i) {
            float bv = 3.402823466e38f; int bi = 0;
#pragma unroll
            for (int j = 0; j < 4; ++j) {
                int c = ctb + cg * 4 + j;
                float s = fmaf(-2.f, dots[i][j], p2t[cg * 4 + j]);
                if (s < bv) { bv = s; bi = c; }
            }
            cand[(pg * 2 + i) * 16 + cg] =
                ((unsigned long long)f2ord(bv) << 32) | (unsigned)bi;
        }
        __syncthreads();
        if (tid < 32 && tid < pcnt) {
            unsigned long long m = cand[tid * 16];
#pragma unroll 8
            for (int t = 1; t < 16; ++t) {
                unsigned long long k2 = cand[tid * 16 + t];
                m = (k2 < m) ? k2 : m;
            }
            atomicMin(&g_best[base + tid], m);
        }
    }
}

// ---------------------------------------------------------------------------
// Kernel 4b: writeback — decode per-point key, compute x2, store outputs.
// ---------------------------------------------------------------------------
__global__ __launch_bounds__(256) void refine_write(const float* __restrict__ X,
                                                    float* __restrict__ out) {
    const int lane = threadIdx.x & 31;
    const int gw = (blockIdx.x * 256 + threadIdx.x) >> 5;
    const int nw = gridDim.x * 8;
    const int nwork = g_cnt;

    for (int w = gw; w < nwork; w += nw) {
        const int gr = g_list[w];
        unsigned long long key = g_best[w];
        int bi = (int)(unsigned)(key & 0xFFFFFFFFull);
        float bv = ord2f((unsigned)(key >> 32));
        const float4* xr = reinterpret_cast<const float4*>(&X[(size_t)gr * DDIM]);
        float4 a = xr[lane];
        float4 b = xr[lane + 32];
        float x2 = a.x * a.x + a.y * a.y + a.z * a.z + a.w * a.w
                 + b.x * b.x + b.y * b.y + b.z * b.z + b.w * b.w;
#pragma unroll
        for (int o = 16; o > 0; o >>= 1)
            x2 += __shfl_xor_sync(0xFFFFFFFFu, x2, o);
        if (lane == 0) {
            out[gr]        = (float)bi;
            out[NPTS + gr] = sqrtf(fmaxf(x2 + bv, 0.f));
        }
    }
}

// ---------------------------------------------------------------------------
// Host launcher
// ---------------------------------------------------------------------------
typedef CUresult (*PFN_tmapEncode)(
    CUtensorMap*, CUtensorMapDataType, cuuint32_t, void*,
    const cuuint64_t*, const cuuint64_t*, const cuuint32_t*, const cuuint32_t*,
    CUtensorMapInterleave, CUtensorMapSwizzle, CUtensorMapL2promotion,
    CUtensorMapFloatOOBfill);

static PFN_tmapEncode get_encode_fn() {
    static PFN_tmapEncode fn = nullptr;
    if (!fn) {
        void* p = nullptr;
        cudaDriverEntryPointQueryResult st;
        cudaGetDriverEntryPointByVersion("cuTensorMapEncodeTiled", &p, 12000,
                                         cudaEnableDefault, &st);
        fn = (PFN_tmapEncode)p;
    }
    return fn;
}

static void make_phi_map(CUtensorMap* map, void* ptr) {
    cuuint64_t dims[2]    = {DDIM, CDIM};
    cuuint64_t strides[1] = {DDIM * 2};
    cuuint32_t box[2]     = {64, 128};
    cuuint32_t es[2]      = {1, 1};
    get_encode_fn()(map, CU_TENSOR_MAP_DATA_TYPE_FLOAT16, 2, ptr,
                    dims, strides, box, es,
                    CU_TENSOR_MAP_INTERLEAVE_NONE, CU_TENSOR_MAP_SWIZZLE_128B,
                    CU_TENSOR_MAP_L2_PROMOTION_L2_128B,
                    CU_TENSOR_MAP_FLOAT_OOB_FILL_NONE);
}

extern "C" void kernel_launch(void* const* d_in, const int* in_sizes, int n_in,
                              void* d_out, int out_size) {
    const float* X = (const float*)d_in[0];
    const float* parents = (const float*)d_in[1];
    const float* epsilon = (const float*)d_in[2];
    float* out = (float*)d_out;

    void* cntPtr = nullptr;
    cudaGetSymbolAddress(&cntPtr, g_cnt);
    cudaMemsetAsync(cntPtr, 0, sizeof(int));

    void* phiH = nullptr;
    cudaGetSymbolAddress(&phiH, g_PhiH);
    CUtensorMap tmapH;
    make_phi_map(&tmapH, phiH);

    phi_kernel<<<dim3(DDIM / 32, CDIM / 32), 256>>>(parents, epsilon);

    static bool attrSet = false;   // idempotent attribute set (not a guard on work)
    if (!attrSet) {
        cudaFuncSetAttribute(dist_kernel, cudaFuncAttributeMaxDynamicSharedMemorySize,
                             SMEM_TOTAL);
        cudaFuncSetAttribute(refine_score, cudaFuncAttributeMaxDynamicSharedMemorySize,
                             RS_SMEM);
        attrSet = true;
    }
    dist_kernel<<<(NPTS + 127) / 128, 256, SMEM_TOTAL>>>(X, out, tmapH);
    refine_score<<<1184, 256, RS_SMEM>>>(X);
    refine_write<<<64, 256>>>(X, out);
}

// round 16
// speedup vs baseline: 1.3647x; 1.3647x over previous
#include <cuda_runtime.h>
#include <cuda.h>
#include <cuda_fp16.h>
#include <math.h>

#define NPTS 100000
#define CDIM 1024
#define DDIM 256
#define THRESH 8.0f

// Scratch (no allocations allowed)
__device__ __align__(16) float g_Phi[CDIM * DDIM];
__device__ __align__(16) __half g_PhiH[CDIM * DDIM];
__device__ float g_p2[CDIM];
__device__ int g_cnt;
__device__ int g_list[NPTS];
__device__ unsigned long long g_best[NPTS];

// ---------------------------------------------------------------------------
// PTX helpers (sm_100-safe: mma.sync + TMA + mbarrier only)
// ---------------------------------------------------------------------------
static __device__ __forceinline__ unsigned smem_u32(const void* p) {
    return (unsigned)__cvta_generic_to_shared(p);
}

#define SWZ128(off) ((off) ^ (((off) >> 3) & 0x70))

#define LDSM4(r0, r1, r2, r3, addr)                                            \
    asm volatile("ldmatrix.sync.aligned.m8n8.x4.shared.b16 {%0,%1,%2,%3}, [%4];" \
                 : "=r"(r0), "=r"(r1), "=r"(r2), "=r"(r3) : "r"(addr))

#define MMA16816F16(c, a, b)                                                   \
    asm volatile("mma.sync.aligned.m16n8k16.row.col.f32.f16.f16.f32 "          \
                 "{%0,%1,%2,%3}, {%4,%5,%6,%7}, {%8,%9}, {%0,%1,%2,%3};"       \
                 : "+f"((c)[0]), "+f"((c)[1]), "+f"((c)[2]), "+f"((c)[3])      \
                 : "r"((a)[0]), "r"((a)[1]), "r"((a)[2]), "r"((a)[3]),         \
                   "r"((b)[0]), "r"((b)[1]))

#define MBARRIER_INIT(mbar, cnt) \
    asm volatile("mbarrier.init.shared.b64 [%0], %1;" \
                 :: "r"((unsigned)(mbar)), "r"((unsigned)(cnt)) : "memory")
#define MBARRIER_EXPECT_TX(mbar, b) \
    asm volatile("mbarrier.arrive.expect_tx.shared.b64 _, [%0], %1;" \
                 :: "r"((unsigned)(mbar)), "r"((unsigned)(b)) : "memory")

static __device__ __forceinline__ void mbar_wait(unsigned mbar, unsigned parity) {
    asm volatile(
        "{\n\t"
        ".reg .pred P;\n\t"
        "W_%=:\n\t"
        "mbarrier.try_wait.parity.acquire.cta.shared::cta.b64 P, [%0], %1, 0x989680;\n\t"
        "@P bra D_%=;\n\t"
        "bra W_%=;\n\t"
        "D_%=:\n\t"
        "}"
        :: "r"(mbar), "r"(parity) : "memory");
}

static __device__ __forceinline__ void tma2d(unsigned dst, const CUtensorMap* map,
                                             int x, int y, unsigned mbar) {
    asm volatile(
        "cp.async.bulk.tensor.2d.shared::cta.global.tile.mbarrier::complete_tx::bytes "
        "[%0], [%1, {%2, %3}], [%4];"
        :: "r"(dst), "l"(map), "r"(x), "r"(y), "r"(mbar) : "memory");
}

// Monotonic float <-> ordered-uint encoding (min of key = min score, then idx)
static __device__ __forceinline__ unsigned f2ord(float f) {
    unsigned u = __float_as_uint(f);
    return (u & 0x80000000u) ? ~u : (u | 0x80000000u);
}
static __device__ __forceinline__ float ord2f(unsigned o) {
    unsigned u = (o & 0x80000000u) ? (o ^ 0x80000000u) : ~o;
    return __uint_as_float(u);
}

// ---------------------------------------------------------------------------
// Kernel 1: Phi = parents @ epsilon. Sequential k 0..1023 per element (exact,
// matches reference ordering — DO NOT reassociate; one flip fails the test).
// ---------------------------------------------------------------------------
__global__ __launch_bounds__(256) void phi_kernel(const float* __restrict__ A,
                                                  const float* __restrict__ B) {
    __shared__ __align__(16) float As[16][34];
    __shared__ __align__(16) float Bs[16][36];
    const int tid = threadIdx.x;
    const int tx = tid & 15, ty = tid >> 4;
    const int m0 = blockIdx.y * 32;
    const int n0 = blockIdx.x * 32;
    float acc[2][2] = {};

    for (int k0 = 0; k0 < CDIM; k0 += 16) {
        __syncthreads();
        if (tid < 128) {
            int row = tid >> 2, c4 = tid & 3;
            float4 v = *reinterpret_cast<const float4*>(&A[(m0 + row) * CDIM + k0 + c4 * 4]);
            As[c4 * 4 + 0][row] = v.x;
            As[c4 * 4 + 1][row] = v.y;
            As[c4 * 4 + 2][row] = v.z;
            As[c4 * 4 + 3][row] = v.w;
        } else {
            int t = tid - 128;
            int row = t >> 3, c8 = t & 7;
            float4 v = *reinterpret_cast<const float4*>(&B[(k0 + row) * DDIM + n0 + c8 * 4]);
            Bs[row][c8 * 4 + 0] = v.x;
            Bs[row][c8 * 4 + 1] = v.y;
            Bs[row][c8 * 4 + 2] = v.z;
            Bs[row][c8 * 4 + 3] = v.w;
        }
        __syncthreads();
#pragma unroll
        for (int k = 0; k < 16; ++k) {
            float2 a01 = *reinterpret_cast<const float2*>(&As[k][ty * 2]);
            float2 b01 = *reinterpret_cast<const float2*>(&Bs[k][tx * 2]);
            acc[0][0] = fmaf(a01.x, b01.x, acc[0][0]);
            acc[0][1] = fmaf(a01.x, b01.y, acc[0][1]);
            acc[1][0] = fmaf(a01.y, b01.x, acc[1][0]);
            acc[1][1] = fmaf(a01.y, b01.y, acc[1][1]);
        }
    }
#pragma unroll
    for (int i = 0; i < 2; ++i) {
        float2 v = make_float2(acc[i][0], acc[i][1]);
        *reinterpret_cast<float2*>(&g_Phi[(m0 + ty * 2 + i) * DDIM + n0 + tx * 2]) = v;
    }
}

// ---------------------------------------------------------------------------
// Kernel 2: p2[c] = ||Phi_c||^2 (fp32) + fp16 copy of Phi.
// ---------------------------------------------------------------------------
__global__ __launch_bounds__(256) void p2_kernel() {
    int w = (blockIdx.x * blockDim.x + threadIdx.x) >> 5;
    int lane = threadIdx.x & 31;
    if (w >= CDIM) return;
    const float4* r = reinterpret_cast<const float4*>(&g_Phi[w * DDIM]);
    float4 a = r[lane];
    float4 b = r[lane + 32];
    __half* dh = &g_PhiH[w * DDIM];
    {
        __half2 h0 = __floats2half2_rn(a.x, a.y);
        __half2 h1 = __floats2half2_rn(a.z, a.w);
        *reinterpret_cast<__half2*>(&dh[lane * 4])     = h0;
        *reinterpret_cast<__half2*>(&dh[lane * 4 + 2]) = h1;
        __half2 h2 = __floats2half2_rn(b.x, b.y);
        __half2 h3 = __floats2half2_rn(b.z, b.w);
        *reinterpret_cast<__half2*>(&dh[128 + lane * 4])     = h2;
        *reinterpret_cast<__half2*>(&dh[128 + lane * 4 + 2]) = h3;
    }
    float s = a.x * a.x + a.y * a.y + a.z * a.z + a.w * a.w
            + b.x * b.x + b.y * b.y + b.z * b.z + b.w * b.w;
#pragma unroll
    for (int o = 16; o > 0; o >>= 1)
        s += __shfl_xor_sync(0xFFFFFFFFu, s, o);
    if (lane == 0) g_p2[w] = s;
}

// ---------------------------------------------------------------------------
// Kernel 3: single-pass fp16 mma.sync dots + argmin; Phi via TMA (SW128),
// 3-stage ring. X stored as 4 SW128 chunks. Byte-identical to R14 (329.8us).
// ---------------------------------------------------------------------------
#define X_OFF     0
#define STG_OFF   65536
#define MB_OFF    114688
#define SMEM_TOTAL 114752

__global__ __launch_bounds__(256, 2)
void dist_kernel(const float* __restrict__ X, float* __restrict__ out,
                 const __grid_constant__ CUtensorMap tmapH) {
    extern __shared__ __align__(1024) char smem[];
    const unsigned SB = smem_u32(smem);
    const unsigned MB = SB + MB_OFF;
    float* red_v = reinterpret_cast<float*>(smem + STG_OFF);
    int*   red_i = reinterpret_cast<int*>(smem + STG_OFF + 8192);
    float* red_s = reinterpret_cast<float*>(smem + STG_OFF + 16384);

    const int tid = threadIdx.x;
    const int lane = tid & 31, wid = tid >> 5;
    const int wm = wid >> 2, wn = wid & 3;
    const int mBase = wm * 64, nBase = wn * 32;
    const int rowBase = blockIdx.x * 128;

    if (tid == 0) {
        MBARRIER_INIT(MB + 0, 1);
        MBARRIER_INIT(MB + 8, 1);
        MBARRIER_INIT(MB + 16, 1);
    }

    for (int i = tid; i < 128 * 128; i += 256) {
        int r = i >> 7, kp = i & 127;
        int k = kp * 2;
        int gr = rowBase + r;
        float2 v = make_float2(0.f, 0.f);
        if (gr < NPTS)
            v = *reinterpret_cast<const float2*>(&X[(size_t)gr * DDIM + k]);
        int chunk = k >> 6, kin = k & 63;
        unsigned sw = SWZ128((unsigned)(r * 128 + kin * 2));
        *reinterpret_cast<__half2*>(smem + X_OFF + chunk * 16384 + sw) =
            __floats2half2_rn(v.x, v.y);
    }
    __syncthreads();

    if (tid == 0) {
#pragma unroll
        for (int g = 0; g < 3; ++g) {
            MBARRIER_EXPECT_TX(MB + (unsigned)g * 8, 16384);
            tma2d(SB + STG_OFF + (unsigned)g * 16384, &tmapH,
                  (g & 3) * 64, (g >> 2) * 128, MB + (unsigned)g * 8);
        }
    }

    const int arow = lane & 15;
    const int ahalf = lane >> 4;
    const int brow = (lane & 7) | ((lane >> 1) & 8);
    const int bhalf = (lane >> 3) & 1;

    int rowb[4];
#pragma unroll
    for (int mt = 0; mt < 4; ++mt)
        rowb[mt] = (mBase + mt * 16 + arow) * 128;

    float bestv[8], secondv[8];
    int   besti[8];
#pragma unroll
    for (int i = 0; i < 8; ++i) {
        bestv[i] = 3.402823466e38f; secondv[i] = 3.402823466e38f; besti[i] = 0;
    }

    float acc[4][4][4];
#pragma unroll
    for (int mt = 0; mt < 4; ++mt)
#pragma unroll
        for (int nt = 0; nt < 4; ++nt)
#pragma unroll
            for (int e = 0; e < 4; ++e) acc[mt][nt][e] = 0.f;

    for (int g = 0; g < 32; ++g) {                   // g = ct*4 + kc
        const int s = g % 3;
        const int f = g / 3;
        const int kc = g & 3;
        mbar_wait(MB + (unsigned)s * 8, (unsigned)(f & 1));
        const unsigned stH = SB + STG_OFF + (unsigned)s * 16384;
        const unsigned xCh = SB + X_OFF + (unsigned)kc * 16384;
#pragma unroll
        for (int ks = 0; ks < 4; ++ks) {
            unsigned ah[4][4];
#pragma unroll
            for (int mt = 0; mt < 4; ++mt) {
                unsigned o = SWZ128((unsigned)(rowb[mt] + ks * 32 + ahalf * 16));
                LDSM4(ah[mt][0], ah[mt][1], ah[mt][2], ah[mt][3], xCh + o);
            }
            unsigned bh[4][2];
#pragma unroll
            for (int nt2 = 0; nt2 < 2; ++nt2) {
                unsigned off = (unsigned)((nBase + nt2 * 16 + brow) * 128 +
                                          ks * 32 + bhalf * 16);
                off = SWZ128(off);
                LDSM4(bh[nt2 * 2][0], bh[nt2 * 2][1],
                      bh[nt2 * 2 + 1][0], bh[nt2 * 2 + 1][1], stH + off);
            }
#pragma unroll
            for (int mt = 0; mt < 4; ++mt)
#pragma unroll
                for (int nt = 0; nt < 4; ++nt)
                    MMA16816F16(acc[mt][nt], ah[mt], bh[nt]);
        }
        __syncthreads();
        if (tid == 0 && g + 3 < 32) {
            int g2 = g + 3;
            MBARRIER_EXPECT_TX(MB + (unsigned)s * 8, 16384);
            tma2d(SB + STG_OFF + (unsigned)s * 16384, &tmapH,
                  (g2 & 3) * 64, (g2 >> 2) * 128, MB + (unsigned)s * 8);
        }
        if (kc == 3) {
            const int colBase = (g >> 2) * 128;
#pragma unroll
            for (int nt = 0; nt < 4; ++nt) {
                int c0 = colBase + nBase + nt * 8 + (lane & 3) * 2;
                float p2a = __ldg(&g_p2[c0]);
                float p2b = __ldg(&g_p2[c0 + 1]);
#pragma unroll
                for (int mt = 0; mt < 4; ++mt) {
                    float sc[4];
                    sc[0] = fmaf(-2.f, acc[mt][nt][0], p2a);
                    sc[1] = fmaf(-2.f, acc[mt][nt][1], p2b);
                    sc[2] = fmaf(-2.f, acc[mt][nt][2], p2a);
                    sc[3] = fmaf(-2.f, acc[mt][nt][3], p2b);
#pragma unroll
                    for (int e = 0; e < 4; ++e) {
                        int slot = mt * 2 + (e >> 1);
                        int c = c0 + (e & 1);
                        if (sc[e] < bestv[slot]) {
                            secondv[slot] = bestv[slot];
                            bestv[slot] = sc[e]; besti[slot] = c;
                        } else if (sc[e] < secondv[slot]) {
                            secondv[slot] = sc[e];
                        }
                        acc[mt][nt][e] = 0.f;
                    }
                }
            }
        }
    }

    __syncthreads();
#pragma unroll
    for (int mt = 0; mt < 4; ++mt)
#pragma unroll
        for (int h = 0; h < 2; ++h) {
            int r = mBase + mt * 16 + (lane >> 2) + h * 8;
            red_v[r * 16 + wn * 4 + (lane & 3)] = bestv[mt * 2 + h];
            red_i[r * 16 + wn * 4 + (lane & 3)] = besti[mt * 2 + h];
            red_s[r * 16 + wn * 4 + (lane & 3)] = secondv[mt * 2 + h];
        }
    __syncthreads();

    if (tid < 128) {
        int gr = rowBase + tid;
        if (gr < NPTS) {
            float bv = red_v[tid * 16];
            int   bi = red_i[tid * 16];
            float sv = red_s[tid * 16];
#pragma unroll
            for (int t = 1; t < 16; ++t) {
                float v  = red_v[tid * 16 + t];
                int   ii = red_i[tid * 16 + t];
                float s2 = red_s[tid * 16 + t];
                if (v < bv || (v == bv && ii < bi)) {
                    sv = fminf(s2, bv);
                    bv = v; bi = ii;
                } else {
                    sv = fminf(sv, v);
                }
            }
            if (sv - bv < THRESH) {            // near-tie -> exact refinement
                int w = atomicAdd(&g_cnt, 1);
                g_list[w] = gr;
                g_best[w] = 0xFFFFFFFFFFFFFFFFull;
            }
            const float4* xr = reinterpret_cast<const float4*>(&X[(size_t)gr * DDIM]);
            float x2 = 0.f;
#pragma unroll 8
            for (int t = 0; t < 64; ++t) {
                float4 v = xr[t];
                x2 += v.x * v.x + v.y * v.y + v.z * v.z + v.w * v.w;
            }
            float d2 = fmaxf(x2 + bv, 0.f);
            out[gr]        = (float)bi;
            out[NPTS + gr] = sqrtf(d2);
        }
    }
}

// ---------------------------------------------------------------------------
// Kernel 4a: exact fp32 refinement, BATCHED + register-blocked, 64-cent tiles.
// Task = (32-point tile) x (64-centroid tile). Thread = 2 pts x 4 cents.
// smem: xk[256][36] f32 | phk[64][68] f32 | cand[32][16] u64
// ---------------------------------------------------------------------------
#define RS_XK    0
#define RS_PH    36864
#define RS_CAND  (RS_PH + 17408)          // 54272
#define RS_SMEM  (RS_CAND + 4096)         // 58368

__global__ __launch_bounds__(256) void refine_score(const float* __restrict__ X) {
    extern __shared__ __align__(16) char rsm[];
    float* xk  = reinterpret_cast<float*>(rsm + RS_XK);     // [256][36]
    float* phk = reinterpret_cast<float*>(rsm + RS_PH);     // [64][68]
    unsigned long long* cand = reinterpret_cast<unsigned long long*>(rsm + RS_CAND);

    const int tid = threadIdx.x;
    const int pg = tid & 15;         // point group: 2 points
    const int cg = tid >> 4;         // centroid group: 4 centroids (16 groups)
    const int cnt = g_cnt;
    const int ptiles = (cnt + 31) >> 5;
    const int ntask = ptiles * 16;

    for (int task = blockIdx.x; task < ntask; task += gridDim.x) {
        const int base = (task >> 4) * 32;
        const int ctb = (task & 15) * 64;
        const int pcnt = min(32, cnt - base);
        __syncthreads();                       // protect smem reuse
        // Load 32 point rows transposed into xk[k][p]
        for (int i = tid; i < 32 * 64; i += 256) {
            int p = i >> 6, f4 = i & 63;
            float4 v = make_float4(0.f, 0.f, 0.f, 0.f);
            if (p < pcnt)
                v = reinterpret_cast<const float4*>(
                        &X[(size_t)g_list[base + p] * DDIM])[f4];
            xk[(f4 * 4 + 0) * 36 + p] = v.x;
            xk[(f4 * 4 + 1) * 36 + p] = v.y;
            xk[(f4 * 4 + 2) * 36 + p] = v.z;
            xk[(f4 * 4 + 3) * 36 + p] = v.w;
        }
        float dots[2][4];
#pragma unroll
        for (int i = 0; i < 2; ++i)
#pragma unroll
            for (int j = 0; j < 4; ++j) dots[i][j] = 0.f;

        for (int ch = 0; ch < 4; ++ch) {       // k chunks of 64
            __syncthreads();
            for (int i = tid; i < 64 * 16; i += 256) {
                int c = i >> 4, f4 = i & 15;
                float4 v = reinterpret_cast<const float4*>(
                    &g_Phi[(size_t)(ctb + c) * DDIM + ch * 64])[f4];
                phk[(f4 * 4 + 0) * 68 + c] = v.x;
                phk[(f4 * 4 + 1) * 68 + c] = v.y;
                phk[(f4 * 4 + 2) * 68 + c] = v.z;
                phk[(f4 * 4 + 3) * 68 + c] = v.w;
            }
            __syncthreads();
#pragma unroll 8
            for (int kk = 0; kk < 64; ++kk) {
                float2 xv = *reinterpret_cast<const float2*>(
                    &xk[(ch * 64 + kk) * 36 + pg * 2]);
                float4 pv = *reinterpret_cast<const float4*>(
                    &phk[kk * 68 + cg * 4]);
                float xa[2] = {xv.x, xv.y};
                float pa[4] = {pv.x, pv.y, pv.z, pv.w};
#pragma unroll
                for (int i = 0; i < 2; ++i)
#pragma unroll
                    for (int j = 0; j < 4; ++j)
                        dots[i][j] = fmaf(xa[i], pa[j], dots[i][j]);
            }
        }
        // Per-thread argmin over its 4 centroids per point (c ascending)
#pragma unroll
        for (int i = 0; i < 2; ++i) {
            float bv = 3.402823466e38f; int bi = 0;
#pragma unroll
            for (int j = 0; j < 4; ++j) {
                int c = ctb + cg * 4 + j;
                float s = fmaf(-2.f, dots[i][j], __ldg(&g_p2[c]));
                if (s < bv) { bv = s; bi = c; }
            }
            cand[(pg * 2 + i) * 16 + cg] =
                ((unsigned long long)f2ord(bv) << 32) | (unsigned)bi;
        }
        __syncthreads();
        if (tid < 32 && tid < pcnt) {
            unsigned long long m = cand[tid * 16];
#pragma unroll 8
            for (int t = 1; t < 16; ++t) {
                unsigned long long k2 = cand[tid * 16 + t];
                m = (k2 < m) ? k2 : m;
            }
            atomicMin(&g_best[base + tid], m);
        }
    }
}

// ---------------------------------------------------------------------------
// Kernel 4b: writeback — decode per-point key, compute x2, store outputs.
// ---------------------------------------------------------------------------
__global__ __launch_bounds__(256) void refine_write(const float* __restrict__ X,
                                                    float* __restrict__ out) {
    const int lane = threadIdx.x & 31;
    const int gw = (blockIdx.x * 256 + threadIdx.x) >> 5;
    const int nw = gridDim.x * 8;
    const int nwork = g_cnt;

    for (int w = gw; w < nwork; w += nw) {
        const int gr = g_list[w];
        unsigned long long key = g_best[w];
        int bi = (int)(unsigned)(key & 0xFFFFFFFFull);
        float bv = ord2f((unsigned)(key >> 32));
        const float4* xr = reinterpret_cast<const float4*>(&X[(size_t)gr * DDIM]);
        float4 a = xr[lane];
        float4 b = xr[lane + 32];
        float x2 = a.x * a.x + a.y * a.y + a.z * a.z + a.w * a.w
                 + b.x * b.x + b.y * b.y + b.z * b.z + b.w * b.w;
#pragma unroll
        for (int o = 16; o > 0; o >>= 1)
            x2 += __shfl_xor_sync(0xFFFFFFFFu, x2, o);
        if (lane == 0) {
            out[gr]        = (float)bi;
            out[NPTS + gr] = sqrtf(fmaxf(x2 + bv, 0.f));
        }
    }
}

// ---------------------------------------------------------------------------
// Host launcher
// ---------------------------------------------------------------------------
typedef CUresult (*PFN_tmapEncode)(
    CUtensorMap*, CUtensorMapDataType, cuuint32_t, void*,
    const cuuint64_t*, const cuuint64_t*, const cuuint32_t*, const cuuint32_t*,
    CUtensorMapInterleave, CUtensorMapSwizzle, CUtensorMapL2promotion,
    CUtensorMapFloatOOBfill);

static PFN_tmapEncode get_encode_fn() {
    static PFN_tmapEncode fn = nullptr;
    if (!fn) {
        void* p = nullptr;
        cudaDriverEntryPointQueryResult st;
        cudaGetDriverEntryPointByVersion("cuTensorMapEncodeTiled", &p, 12000,
                                         cudaEnableDefault, &st);
        fn = (PFN_tmapEncode)p;
    }
    return fn;
}

static void make_phi_map(CUtensorMap* map, void* ptr) {
    cuuint64_t dims[2]    = {DDIM, CDIM};
    cuuint64_t strides[1] = {DDIM * 2};
    cuuint32_t box[2]     = {64, 128};
    cuuint32_t es[2]      = {1, 1};
    get_encode_fn()(map, CU_TENSOR_MAP_DATA_TYPE_FLOAT16, 2, ptr,
                    dims, strides, box, es,
                    CU_TENSOR_MAP_INTERLEAVE_NONE, CU_TENSOR_MAP_SWIZZLE_128B,
                    CU_TENSOR_MAP_L2_PROMOTION_L2_128B,
                    CU_TENSOR_MAP_FLOAT_OOB_FILL_NONE);
}

extern "C" void kernel_launch(void* const* d_in, const int* in_sizes, int n_in,
                              void* d_out, int out_size) {
    const float* X = (const float*)d_in[0];
    const float* parents = (const float*)d_in[1];
    const float* epsilon = (const float*)d_in[2];
    float* out = (float*)d_out;

    void* cntPtr = nullptr;
    cudaGetSymbolAddress(&cntPtr, g_cnt);
    cudaMemsetAsync(cntPtr, 0, sizeof(int));

    void* phiH = nullptr;
    cudaGetSymbolAddress(&phiH, g_PhiH);
    CUtensorMap tmapH;
    make_phi_map(&tmapH, phiH);

    phi_kernel<<<dim3(DDIM / 32, CDIM / 32), 256>>>(parents, epsilon);
    p2_kernel<<<(CDIM * 32) / 256, 256>>>();

    static bool attrSet = false;   // idempotent attribute set (not a guard on work)
    if (!attrSet) {
        cudaFuncSetAttribute(dist_kernel, cudaFuncAttributeMaxDynamicSharedMemorySize,
                             SMEM_TOTAL);
        cudaFuncSetAttribute(refine_score, cudaFuncAttributeMaxDynamicSharedMemorySize,
                             RS_SMEM);
        attrSet = true;
    }
    dist_kernel<<<(NPTS + 127) / 128, 256, SMEM_TOTAL>>>(X, out, tmapH);
    refine_score<<<1184, 256, RS_SMEM>>>(X);
    refine_write<<<64, 256>>>(X, out);
}

// round 17
// speedup vs baseline: 1.3649x; 1.0001x over previous
#include <cuda_runtime.h>
#include <cuda.h>
#include <cuda_fp16.h>
#include <math.h>

#define NPTS 100000
#define CDIM 1024
#define DDIM 256
#define THRESH 8.0f

// Scratch (no allocations allowed)
__device__ __align__(16) float g_Phi[CDIM * DDIM];
__device__ __align__(16) __half g_PhiH[CDIM * DDIM];
__device__ float g_p2[CDIM];
__device__ int g_cnt;
__device__ int g_list[NPTS];
__device__ unsigned long long g_best[NPTS];

// ---------------------------------------------------------------------------
// PTX helpers (sm_100-safe: mma.sync + TMA + mbarrier only)
// ---------------------------------------------------------------------------
static __device__ __forceinline__ unsigned smem_u32(const void* p) {
    return (unsigned)__cvta_generic_to_shared(p);
}

#define SWZ128(off) ((off) ^ (((off) >> 3) & 0x70))

#define LDSM4(r0, r1, r2, r3, addr)                                            \
    asm volatile("ldmatrix.sync.aligned.m8n8.x4.shared.b16 {%0,%1,%2,%3}, [%4];" \
                 : "=r"(r0), "=r"(r1), "=r"(r2), "=r"(r3) : "r"(addr))

#define MMA16816F16(c, a, b)                                                   \
    asm volatile("mma.sync.aligned.m16n8k16.row.col.f32.f16.f16.f32 "          \
                 "{%0,%1,%2,%3}, {%4,%5,%6,%7}, {%8,%9}, {%0,%1,%2,%3};"       \
                 : "+f"((c)[0]), "+f"((c)[1]), "+f"((c)[2]), "+f"((c)[3])      \
                 : "r"((a)[0]), "r"((a)[1]), "r"((a)[2]), "r"((a)[3]),         \
                   "r"((b)[0]), "r"((b)[1]))

#define MBARRIER_INIT(mbar, cnt) \
    asm volatile("mbarrier.init.shared.b64 [%0], %1;" \
                 :: "r"((unsigned)(mbar)), "r"((unsigned)(cnt)) : "memory")
#define MBARRIER_EXPECT_TX(mbar, b) \
    asm volatile("mbarrier.arrive.expect_tx.shared.b64 _, [%0], %1;" \
                 :: "r"((unsigned)(mbar)), "r"((unsigned)(b)) : "memory")

static __device__ __forceinline__ void mbar_wait(unsigned mbar, unsigned parity) {
    asm volatile(
        "{\n\t"
        ".reg .pred P;\n\t"
        "W_%=:\n\t"
        "mbarrier.try_wait.parity.acquire.cta.shared::cta.b64 P, [%0], %1, 0x989680;\n\t"
        "@P bra D_%=;\n\t"
        "bra W_%=;\n\t"
        "D_%=:\n\t"
        "}"
        :: "r"(mbar), "r"(parity) : "memory");
}

static __device__ __forceinline__ void tma2d(unsigned dst, const CUtensorMap* map,
                                             int x, int y, unsigned mbar) {
    asm volatile(
        "cp.async.bulk.tensor.2d.shared::cta.global.tile.mbarrier::complete_tx::bytes "
        "[%0], [%1, {%2, %3}], [%4];"
        :: "r"(dst), "l"(map), "r"(x), "r"(y), "r"(mbar) : "memory");
}

// Monotonic float <-> ordered-uint encoding (min of key = min score, then idx)
static __device__ __forceinline__ unsigned f2ord(float f) {
    unsigned u = __float_as_uint(f);
    return (u & 0x80000000u) ? ~u : (u | 0x80000000u);
}
static __device__ __forceinline__ float ord2f(unsigned o) {
    unsigned u = (o & 0x80000000u) ? (o ^ 0x80000000u) : ~o;
    return __uint_as_float(u);
}

// ---------------------------------------------------------------------------
// Kernel 1: Phi = parents @ epsilon. Sequential k 0..1023 per element (exact,
// matches reference ordering — DO NOT reassociate; one flip fails the test).
// ---------------------------------------------------------------------------
__global__ __launch_bounds__(256) void phi_kernel(const float* __restrict__ A,
                                                  const float* __restrict__ B) {
    __shared__ __align__(16) float As[16][34];
    __shared__ __align__(16) float Bs[16][36];
    const int tid = threadIdx.x;
    const int tx = tid & 15, ty = tid >> 4;
    const int m0 = blockIdx.y * 32;
    const int n0 = blockIdx.x * 32;
    float acc[2][2] = {};

    for (int k0 = 0; k0 < CDIM; k0 += 16) {
        __syncthreads();
        if (tid < 128) {
            int row = tid >> 2, c4 = tid & 3;
            float4 v = *reinterpret_cast<const float4*>(&A[(m0 + row) * CDIM + k0 + c4 * 4]);
            As[c4 * 4 + 0][row] = v.x;
            As[c4 * 4 + 1][row] = v.y;
            As[c4 * 4 + 2][row] = v.z;
            As[c4 * 4 + 3][row] = v.w;
        } else {
            int t = tid - 128;
            int row = t >> 3, c8 = t & 7;
            float4 v = *reinterpret_cast<const float4*>(&B[(k0 + row) * DDIM + n0 + c8 * 4]);
            Bs[row][c8 * 4 + 0] = v.x;
            Bs[row][c8 * 4 + 1] = v.y;
            Bs[row][c8 * 4 + 2] = v.z;
            Bs[row][c8 * 4 + 3] = v.w;
        }
        __syncthreads();
#pragma unroll
        for (int k = 0; k < 16; ++k) {
            float2 a01 = *reinterpret_cast<const float2*>(&As[k][ty * 2]);
            float2 b01 = *reinterpret_cast<const float2*>(&Bs[k][tx * 2]);
            acc[0][0] = fmaf(a01.x, b01.x, acc[0][0]);
            acc[0][1] = fmaf(a01.x, b01.y, acc[0][1]);
            acc[1][0] = fmaf(a01.y, b01.x, acc[1][0]);
            acc[1][1] = fmaf(a01.y, b01.y, acc[1][1]);
        }
    }
#pragma unroll
    for (int i = 0; i < 2; ++i) {
        float2 v = make_float2(acc[i][0], acc[i][1]);
        *reinterpret_cast<float2*>(&g_Phi[(m0 + ty * 2 + i) * DDIM + n0 + tx * 2]) = v;
    }
}

// ---------------------------------------------------------------------------
// Kernel 2: p2[c] = ||Phi_c||^2 (fp32) + fp16 copy of Phi.
// ---------------------------------------------------------------------------
__global__ __launch_bounds__(256) void p2_kernel() {
    int w = (blockIdx.x * blockDim.x + threadIdx.x) >> 5;
    int lane = threadIdx.x & 31;
    if (w >= CDIM) return;
    const float4* r = reinterpret_cast<const float4*>(&g_Phi[w * DDIM]);
    float4 a = r[lane];
    float4 b = r[lane + 32];
    __half* dh = &g_PhiH[w * DDIM];
    {
        __half2 h0 = __floats2half2_rn(a.x, a.y);
        __half2 h1 = __floats2half2_rn(a.z, a.w);
        *reinterpret_cast<__half2*>(&dh[lane * 4])     = h0;
        *reinterpret_cast<__half2*>(&dh[lane * 4 + 2]) = h1;
        __half2 h2 = __floats2half2_rn(b.x, b.y);
        __half2 h3 = __floats2half2_rn(b.z, b.w);
        *reinterpret_cast<__half2*>(&dh[128 + lane * 4])     = h2;
        *reinterpret_cast<__half2*>(&dh[128 + lane * 4 + 2]) = h3;
    }
    float s = a.x * a.x + a.y * a.y + a.z * a.z + a.w * a.w
            + b.x * b.x + b.y * b.y + b.z * b.z + b.w * b.w;
#pragma unroll
    for (int o = 16; o > 0; o >>= 1)
        s += __shfl_xor_sync(0xFFFFFFFFu, s, o);
    if (lane == 0) g_p2[w] = s;
}

// ---------------------------------------------------------------------------
// Kernel 3: single-pass fp16 mma.sync dots + argmin; Phi via TMA (SW128),
// 2-stage ring (R8/R11-validated protocol), X as 4 SW128 chunks.
// SMEM = 98368 B -> 2 CTAs/SM genuinely resident.
// ---------------------------------------------------------------------------
#define X_OFF     0
#define STG_OFF   65536
#define MB_OFF    98304
#define SMEM_TOTAL 98368

__global__ __launch_bounds__(256, 2)
void dist_kernel(const float* __restrict__ X, float* __restrict__ out,
                 const __grid_constant__ CUtensorMap tmapH) {
    extern __shared__ __align__(1024) char smem[];
    const unsigned SB = smem_u32(smem);
    const unsigned MB = SB + MB_OFF;
    float* red_v = reinterpret_cast<float*>(smem + STG_OFF);
    int*   red_i = reinterpret_cast<int*>(smem + STG_OFF + 8192);
    float* red_s = reinterpret_cast<float*>(smem + STG_OFF + 16384);

    const int tid = threadIdx.x;
    const int lane = tid & 31, wid = tid >> 5;
    const int wm = wid >> 2, wn = wid & 3;
    const int mBase = wm * 64, nBase = wn * 32;
    const int rowBase = blockIdx.x * 128;

    if (tid == 0) {
        MBARRIER_INIT(MB + 0, 1);
        MBARRIER_INIT(MB + 8, 1);
    }

    for (int i = tid; i < 128 * 128; i += 256) {
        int r = i >> 7, kp = i & 127;
        int k = kp * 2;
        int gr = rowBase + r;
        float2 v = make_float2(0.f, 0.f);
        if (gr < NPTS)
            v = *reinterpret_cast<const float2*>(&X[(size_t)gr * DDIM + k]);
        int chunk = k >> 6, kin = k & 63;
        unsigned sw = SWZ128((unsigned)(r * 128 + kin * 2));
        *reinterpret_cast<__half2*>(smem + X_OFF + chunk * 16384 + sw) =
            __floats2half2_rn(v.x, v.y);
    }
    __syncthreads();

    if (tid == 0) {
#pragma unroll
        for (int g = 0; g < 2; ++g) {
            MBARRIER_EXPECT_TX(MB + (unsigned)g * 8, 16384);
            tma2d(SB + STG_OFF + (unsigned)g * 16384, &tmapH,
                  (g & 3) * 64, (g >> 2) * 128, MB + (unsigned)g * 8);
        }
    }

    const int arow = lane & 15;
    const int ahalf = lane >> 4;
    const int brow = (lane & 7) | ((lane >> 1) & 8);
    const int bhalf = (lane >> 3) & 1;

    int rowb[4];
#pragma unroll
    for (int mt = 0; mt < 4; ++mt)
        rowb[mt] = (mBase + mt * 16 + arow) * 128;

    float bestv[8], secondv[8];
    int   besti[8];
#pragma unroll
    for (int i = 0; i < 8; ++i) {
        bestv[i] = 3.402823466e38f; secondv[i] = 3.402823466e38f; besti[i] = 0;
    }

    float acc[4][4][4];
#pragma unroll
    for (int mt = 0; mt < 4; ++mt)
#pragma unroll
        for (int nt = 0; nt < 4; ++nt)
#pragma unroll
            for (int e = 0; e < 4; ++e) acc[mt][nt][e] = 0.f;

    for (int g = 0; g < 32; ++g) {                   // g = ct*4 + kc
        const int s = g & 1;                          // stage
        const int kc = g & 3;
        mbar_wait(MB + (unsigned)s * 8, (unsigned)((g >> 1) & 1));
        const unsigned stH = SB + STG_OFF + (unsigned)s * 16384;
        const unsigned xCh = SB + X_OFF + (unsigned)kc * 16384;
#pragma unroll
        for (int ks = 0; ks < 4; ++ks) {
            unsigned ah[4][4];
#pragma unroll
            for (int mt = 0; mt < 4; ++mt) {
                unsigned o = SWZ128((unsigned)(rowb[mt] + ks * 32 + ahalf * 16));
                LDSM4(ah[mt][0], ah[mt][1], ah[mt][2], ah[mt][3], xCh + o);
            }
            unsigned bh[4][2];
#pragma unroll
            for (int nt2 = 0; nt2 < 2; ++nt2) {
                unsigned off = (unsigned)((nBase + nt2 * 16 + brow) * 128 +
                                          ks * 32 + bhalf * 16);
                off = SWZ128(off);
                LDSM4(bh[nt2 * 2][0], bh[nt2 * 2][1],
                      bh[nt2 * 2 + 1][0], bh[nt2 * 2 + 1][1], stH + off);
            }
#pragma unroll
            for (int mt = 0; mt < 4; ++mt)
#pragma unroll
                for (int nt = 0; nt < 4; ++nt)
                    MMA16816F16(acc[mt][nt], ah[mt], bh[nt]);
        }
        __syncthreads();                             // stage s fully consumed
        if (tid == 0 && g + 2 < 32) {
            int g2 = g + 2;
            MBARRIER_EXPECT_TX(MB + (unsigned)s * 8, 16384);
            tma2d(SB + STG_OFF + (unsigned)s * 16384, &tmapH,
                  (g2 & 3) * 64, (g2 >> 2) * 128, MB + (unsigned)s * 8);
        }
        if (kc == 3) {
            const int colBase = (g >> 2) * 128;
#pragma unroll
            for (int nt = 0; nt < 4; ++nt) {
                int c0 = colBase + nBase + nt * 8 + (lane & 3) * 2;
                float p2a = __ldg(&g_p2[c0]);
                float p2b = __ldg(&g_p2[c0 + 1]);
#pragma unroll
                for (int mt = 0; mt < 4; ++mt) {
                    float sc[4];
                    sc[0] = fmaf(-2.f, acc[mt][nt][0], p2a);
                    sc[1] = fmaf(-2.f, acc[mt][nt][1], p2b);
                    sc[2] = fmaf(-2.f, acc[mt][nt][2], p2a);
                    sc[3] = fmaf(-2.f, acc[mt][nt][3], p2b);
#pragma unroll
                    for (int e = 0; e < 4; ++e) {
                        int slot = mt * 2 + (e >> 1);
                        int c = c0 + (e & 1);
                        if (sc[e] < bestv[slot]) {
                            secondv[slot] = bestv[slot];
                            bestv[slot] = sc[e]; besti[slot] = c;
                        } else if (sc[e] < secondv[slot]) {
                            secondv[slot] = sc[e];
                        }
                        acc[mt][nt][e] = 0.f;
                    }
                }
            }
        }
    }

    __syncthreads();
#pragma unroll
    for (int mt = 0; mt < 4; ++mt)
#pragma unroll
        for (int h = 0; h < 2; ++h) {
            int r = mBase + mt * 16 + (lane >> 2) + h * 8;
            red_v[r * 16 + wn * 4 + (lane & 3)] = bestv[mt * 2 + h];
            red_i[r * 16 + wn * 4 + (lane & 3)] = besti[mt * 2 + h];
            red_s[r * 16 + wn * 4 + (lane & 3)] = secondv[mt * 2 + h];
        }
    __syncthreads();

    if (tid < 128) {
        int gr = rowBase + tid;
        if (gr < NPTS) {
            float bv = red_v[tid * 16];
            int   bi = red_i[tid * 16];
            float sv = red_s[tid * 16];
#pragma unroll
            for (int t = 1; t < 16; ++t) {
                float v  = red_v[tid * 16 + t];
                int   ii = red_i[tid * 16 + t];
                float s2 = red_s[tid * 16 + t];
                if (v < bv || (v == bv && ii < bi)) {
                    sv = fminf(s2, bv);
                    bv = v; bi = ii;
                } else {
                    sv = fminf(sv, v);
                }
            }
            if (sv - bv < THRESH) {            // near-tie -> exact refinement
                int w = atomicAdd(&g_cnt, 1);
                g_list[w] = gr;
                g_best[w] = 0xFFFFFFFFFFFFFFFFull;
            }
            const float4* xr = reinterpret_cast<const float4*>(&X[(size_t)gr * DDIM]);
            float x2 = 0.f;
#pragma unroll 8
            for (int t = 0; t < 64; ++t) {
                float4 v = xr[t];
                x2 += v.x * v.x + v.y * v.y + v.z * v.z + v.w * v.w;
            }
            float d2 = fmaxf(x2 + bv, 0.f);
            out[gr]        = (float)bi;
            out[NPTS + gr] = sqrtf(d2);
        }
    }
}

// ---------------------------------------------------------------------------
// Kernel 4a: exact fp32 refinement, BATCHED + register-blocked, 64-cent tiles.
// Task = (32-point tile) x (64-centroid tile). Thread = 2 pts x 4 cents.
// smem: xk[256][36] f32 | phk[64][68] f32 | cand[32][16] u64
// ---------------------------------------------------------------------------
#define RS_XK    0
#define RS_PH    36864
#define RS_CAND  (RS_PH + 17408)          // 54272
#define RS_SMEM  (RS_CAND + 4096)         // 58368

__global__ __launch_bounds__(256) void refine_score(const float* __restrict__ X) {
    extern __shared__ __align__(16) char rsm[];
    float* xk  = reinterpret_cast<float*>(rsm + RS_XK);     // [256][36]
    float* phk = reinterpret_cast<float*>(rsm + RS_PH);     // [64][68]
    unsigned long long* cand = reinterpret_cast<unsigned long long*>(rsm + RS_CAND);

    const int tid = threadIdx.x;
    const int pg = tid & 15;         // point group: 2 points
    const int cg = tid >> 4;         // centroid group: 4 centroids (16 groups)
    const int cnt = g_cnt;
    const int ptiles = (cnt + 31) >> 5;
    const int ntask = ptiles * 16;

    for (int task = blockIdx.x; task < ntask; task += gridDim.x) {
        const int base = (task >> 4) * 32;
        const int ctb = (task & 15) * 64;
        const int pcnt = min(32, cnt - base);
        __syncthreads();                       // protect smem reuse
        for (int i = tid; i < 32 * 64; i += 256) {
            int p = i >> 6, f4 = i & 63;
            float4 v = make_float4(0.f, 0.f, 0.f, 0.f);
            if (p < pcnt)
                v = reinterpret_cast<const float4*>(
                        &X[(size_t)g_list[base + p] * DDIM])[f4];
            xk[(f4 * 4 + 0) * 36 + p] = v.x;
            xk[(f4 * 4 + 1) * 36 + p] = v.y;
            xk[(f4 * 4 + 2) * 36 + p] = v.z;
            xk[(f4 * 4 + 3) * 36 + p] = v.w;
        }
        float dots[2][4];
#pragma unroll
        for (int i = 0; i < 2; ++i)
#pragma unroll
            for (int j = 0; j < 4; ++j) dots[i][j] = 0.f;

        for (int ch = 0; ch < 4; ++ch) {       // k chunks of 64
            __syncthreads();
            for (int i = tid; i < 64 * 16; i += 256) {
                int c = i >> 4, f4 = i & 15;
                float4 v = reinterpret_cast<const float4*>(
                    &g_Phi[(size_t)(ctb + c) * DDIM + ch * 64])[f4];
                phk[(f4 * 4 + 0) * 68 + c] = v.x;
                phk[(f4 * 4 + 1) * 68 + c] = v.y;
                phk[(f4 * 4 + 2) * 68 + c] = v.z;
                phk[(f4 * 4 + 3) * 68 + c] = v.w;
            }
            __syncthreads();
#pragma unroll 8
            for (int kk = 0; kk < 64; ++kk) {
                float2 xv = *reinterpret_cast<const float2*>(
                    &xk[(ch * 64 + kk) * 36 + pg * 2]);
                float4 pv = *reinterpret_cast<const float4*>(
                    &phk[kk * 68 + cg * 4]);
                float xa[2] = {xv.x, xv.y};
                float pa[4] = {pv.x, pv.y, pv.z, pv.w};
#pragma unroll
                for (int i = 0; i < 2; ++i)
#pragma unroll
                    for (int j = 0; j < 4; ++j)
                        dots[i][j] = fmaf(xa[i], pa[j], dots[i][j]);
            }
        }
#pragma unroll
        for (int i = 0; i < 2; ++i) {
            float bv = 3.402823466e38f; int bi = 0;
#pragma unroll
            for (int j = 0; j < 4; ++j) {
                int c = ctb + cg * 4 + j;
                float s = fmaf(-2.f, dots[i][j], __ldg(&g_p2[c]));
                if (s < bv) { bv = s; bi = c; }
            }
            cand[(pg * 2 + i) * 16 + cg] =
                ((unsigned long long)f2ord(bv) << 32) | (unsigned)bi;
        }
        __syncthreads();
        if (tid < 32 && tid < pcnt) {
            unsigned long long m = cand[tid * 16];
#pragma unroll 8
            for (int t = 1; t < 16; ++t) {
                unsigned long long k2 = cand[tid * 16 + t];
                m = (k2 < m) ? k2 : m;
            }
            atomicMin(&g_best[base + tid], m);
        }
    }
}

// ---------------------------------------------------------------------------
// Kernel 4b: writeback — decode per-point key, compute x2, store outputs.
// ---------------------------------------------------------------------------
__global__ __launch_bounds__(256) void refine_write(const float* __restrict__ X,
                                                    float* __restrict__ out) {
    const int lane = threadIdx.x & 31;
    const int gw = (blockIdx.x * 256 + threadIdx.x) >> 5;
    const int nw = gridDim.x * 8;
    const int nwork = g_cnt;

    for (int w = gw; w < nwork; w += nw) {
        const int gr = g_list[w];
        unsigned long long key = g_best[w];
        int bi = (int)(unsigned)(key & 0xFFFFFFFFull);
        float bv = ord2f((unsigned)(key >> 32));
        const float4* xr = reinterpret_cast<const float4*>(&X[(size_t)gr * DDIM]);
        float4 a = xr[lane];
        float4 b = xr[lane + 32];
        float x2 = a.x * a.x + a.y * a.y + a.z * a.z + a.w * a.w
                 + b.x * b.x + b.y * b.y + b.z * b.z + b.w * b.w;
#pragma unroll
        for (int o = 16; o > 0; o >>= 1)
            x2 += __shfl_xor_sync(0xFFFFFFFFu, x2, o);
        if (lane == 0) {
            out[gr]        = (float)bi;
            out[NPTS + gr] = sqrtf(fmaxf(x2 + bv, 0.f));
        }
    }
}

// ---------------------------------------------------------------------------
// Host launcher
// ---------------------------------------------------------------------------
typedef CUresult (*PFN_tmapEncode)(
    CUtensorMap*, CUtensorMapDataType, cuuint32_t, void*,
    const cuuint64_t*, const cuuint64_t*, const cuuint32_t*, const cuuint32_t*,
    CUtensorMapInterleave, CUtensorMapSwizzle, CUtensorMapL2promotion,
    CUtensorMapFloatOOBfill);

static PFN_tmapEncode get_encode_fn() {
    static PFN_tmapEncode fn = nullptr;
    if (!fn) {
        void* p = nullptr;
        cudaDriverEntryPointQueryResult st;
        cudaGetDriverEntryPointByVersion("cuTensorMapEncodeTiled", &p, 12000,
                                         cudaEnableDefault, &st);
        fn = (PFN_tmapEncode)p;
    }
    return fn;
}

static void make_phi_map(CUtensorMap* map, void* ptr) {
    cuuint64_t dims[2]    = {DDIM, CDIM};
    cuuint64_t strides[1] = {DDIM * 2};
    cuuint32_t box[2]     = {64, 128};
    cuuint32_t es[2]      = {1, 1};
    get_encode_fn()(map, CU_TENSOR_MAP_DATA_TYPE_FLOAT16, 2, ptr,
                    dims, strides, box, es,
                    CU_TENSOR_MAP_INTERLEAVE_NONE, CU_TENSOR_MAP_SWIZZLE_128B,
                    CU_TENSOR_MAP_L2_PROMOTION_L2_128B,
                    CU_TENSOR_MAP_FLOAT_OOB_FILL_NONE);
}

extern "C" void kernel_launch(void* const* d_in, const int* in_sizes, int n_in,
                              void* d_out, int out_size) {
    const float* X = (const float*)d_in[0];
    const float* parents = (const float*)d_in[1];
    const float* epsilon = (const float*)d_in[2];
    float* out = (float*)d_out;

    void* cntPtr = nullptr;
    cudaGetSymbolAddress(&cntPtr, g_cnt);
    cudaMemsetAsync(cntPtr, 0, sizeof(int));

    void* phiH = nullptr;
    cudaGetSymbolAddress(&phiH, g_PhiH);
    CUtensorMap tmapH;
    make_phi_map(&tmapH, phiH);

    phi_kernel<<<dim3(DDIM / 32, CDIM / 32), 256>>>(parents, epsilon);
    p2_kernel<<<(CDIM * 32) / 256, 256>>>();

    static bool attrSet = false;   // idempotent attribute set (not a guard on work)
    if (!attrSet) {
        cudaFuncSetAttribute(dist_kernel, cudaFuncAttributeMaxDynamicSharedMemorySize,
                             SMEM_TOTAL);
        cudaFuncSetAttribute(refine_score, cudaFuncAttributeMaxDynamicSharedMemorySize,
                             RS_SMEM);
        attrSet = true;
    }
    dist_kernel<<<(NPTS + 127) / 128, 256, SMEM_TOTAL>>>(X, out, tmapH);
    refine_score<<<1184, 256, RS_SMEM>>>(X);
    refine_write<<<64, 256>>>(X, out);
}